// round 12
// baseline (speedup 1.0000x reference)
#include <cuda_runtime.h>

// Problem constants (fixed shapes: data/noise/rand are (32, 1024, 2048) fp32)
#define DDIM 2048
#define KSEL 512
#define NTHREADS 256
#define NWARPS (NTHREADS / 32)
#define CAND_CAP 64
#define CAND_TARGET 48

__global__ __launch_bounds__(NTHREADS)
void obsmask_kernel(const float* __restrict__ data,
                    const float* __restrict__ noise,
                    const float* __restrict__ rand_vals,
                    float* __restrict__ out_masked,
                    float* __restrict__ out_inv)
{
    const int tid  = threadIdx.x;
    const int lane = tid & 31;
    const int wid  = tid >> 5;
    const size_t base = (size_t)blockIdx.x * DDIM;

    __shared__ unsigned s_wsum[2][NWARPS];   // double-buffered by iteration parity
    __shared__ float s_cval[CAND_CAP];
    __shared__ int   s_cidx[CAND_CAP];
    __shared__ int   s_ccnt;
    __shared__ unsigned char s_mask[DDIM];

    // ---- Issue ALL global loads up front (max MLP; Phase A hides latency).
    //      .cs: streaming loads — data is read exactly once. ----
    const float4* r4 = (const float4*)(rand_vals + base);
    const float4* d4 = (const float4*)(data  + base);
    const float4* n4 = (const float4*)(noise + base);

    float4 ra = __ldcs(&r4[tid]);
    float4 rb = __ldcs(&r4[NTHREADS + tid]);
    float4 da = __ldcs(&d4[tid]);
    float4 db = __ldcs(&d4[NTHREADS + tid]);
    float4 na = __ldcs(&n4[tid]);
    float4 nb = __ldcs(&n4[NTHREADS + tid]);

    float v[8] = { ra.x, ra.y, ra.z, ra.w, rb.x, rb.y, rb.z, rb.w };

    if (tid == 0) s_ccnt = 0;   // covered by Phase A's barrier (>=1 iteration always runs)

    // ---- Phase A: bisection for the k-th-largest bracket ----
    // Invariant: count(v > lo) = c_lo >= K,  count(v > hi) = c_hi < K.
    // rand ~ U[0,1): the 512th largest of 2048 concentrates at 0.75 (sd~0.0096),
    // so iteration 0 probes {0.735, 0.75, 0.765}; ~88% of rows finish in 1 round.
    // ONE barrier per iteration: after it, every thread redundantly sums the
    // 8 per-warp partials (LDS broadcast, conflict-free). Double-buffering
    // s_wsum by parity removes the write-after-read hazard: a warp reaching
    // iter i+1's write must have passed iter i's barrier, so every warp has
    // finished its iter-(i-1) reads of the buffer being overwritten.
    float lo = 0.0f, hi = 1.0f;
    int c_lo = DDIM, c_hi = 0;

    for (int iter = 0; iter < 32 && (c_lo - c_hi) > CAND_TARGET; ++iter) {
        float m1, m2, m3;
        if (iter == 0) { m1 = 0.735f; m2 = 0.75f; m3 = 0.765f; }
        else {
            const float span = hi - lo;
            m1 = lo + 0.25f * span;
            m2 = lo + 0.50f * span;
            m3 = lo + 0.75f * span;
        }

        int c1 = 0, c2 = 0, c3 = 0;
        #pragma unroll
        for (int i = 0; i < 8; ++i) {
            c1 += (v[i] > m1);
            c2 += (v[i] > m2);
            c3 += (v[i] > m3);
        }
        // 10-bit fields: per-warp field sums <= 256, no cross-field carry;
        // block totals <= 2048 > 1023, so unpack per-warp then widen.
        unsigned p = (unsigned)c1 | ((unsigned)c2 << 10) | ((unsigned)c3 << 20);
        p = __reduce_add_sync(0xffffffffu, p);   // REDUX.SUM: 1 instr per warp
        const int buf = iter & 1;
        if (lane == 0) s_wsum[buf][wid] = p;
        __syncthreads();

        int C1 = 0, C2 = 0, C3 = 0;
        #pragma unroll
        for (int w = 0; w < NWARPS; ++w) {
            const unsigned x = s_wsum[buf][w];
            C1 += (int)(x & 1023u);
            C2 += (int)((x >> 10) & 1023u);
            C3 += (int)(x >> 20);
        }

        if (C1 < KSEL)      { hi = m1; c_hi = C1; }
        else if (C2 < KSEL) { lo = m1; c_lo = C1; hi = m2; c_hi = C2; }
        else if (C3 < KSEL) { lo = m2; c_lo = C2; hi = m3; c_hi = C3; }
        else                { lo = m3; c_lo = C3; }
        // All threads compute identical C1/C2/C3 -> uniform branch & exit.
    }

    // ---- Phase B: gather candidates in (lo, hi] ----
    const int r_need = KSEL - c_hi;   // 1 <= r_need <= #candidates
    #pragma unroll
    for (int i = 0; i < 8; ++i) {
        if (v[i] > lo && v[i] <= hi) {
            int slot = atomicAdd(&s_ccnt, 1);
            if (slot < CAND_CAP) {
                s_cval[slot] = v[i];
                s_cidx[slot] = (i < 4) ? (4 * tid + i) : (1024 + 4 * tid + (i - 4));
            }
        }
    }
    __syncthreads();

    // ---- Phase C: exact rank among candidates (ties -> lowest index first) ----
    const int c = min(s_ccnt, CAND_CAP);
    if (tid < c) {
        const float vi = s_cval[tid];
        const int   ii = s_cidx[tid];
        int rank = 0;
        for (int j = 0; j < c; ++j) {
            const float vj = s_cval[j];
            const int   ij = s_cidx[j];
            rank += (vj > vi) || (vj == vi && ij < ii);
        }
        s_mask[ii] = (rank < r_need) ? (unsigned char)1 : (unsigned char)0;
    }
    __syncthreads();

    // ---- Phase D: apply mask, write both outputs (coalesced float4, .cs) ----
    float dd[8] = { da.x, da.y, da.z, da.w, db.x, db.y, db.z, db.w };
    float nn[8] = { na.x, na.y, na.z, na.w, nb.x, nb.y, nb.z, nb.w };
    float om[8], oi[8];

    #pragma unroll
    for (int i = 0; i < 8; ++i) {
        bool m = (v[i] > hi);
        if (!m && v[i] > lo) {
            const int idx = (i < 4) ? (4 * tid + i) : (1024 + 4 * tid + (i - 4));
            m = (s_mask[idx] != 0);
        }
        om[i] = m ? 0.0f : fmaf(0.1f, nn[i], dd[i]);
        oi[i] = m ? 0.0f : 1.0f;
    }

    float4* om4 = (float4*)(out_masked + base);
    float4* oi4 = (float4*)(out_inv    + base);
    __stcs(&om4[tid],            make_float4(om[0], om[1], om[2], om[3]));
    __stcs(&om4[NTHREADS + tid], make_float4(om[4], om[5], om[6], om[7]));
    __stcs(&oi4[tid],            make_float4(oi[0], oi[1], oi[2], oi[3]));
    __stcs(&oi4[NTHREADS + tid], make_float4(oi[4], oi[5], oi[6], oi[7]));
}

extern "C" void kernel_launch(void* const* d_in, const int* in_sizes, int n_in,
                              void* d_out, int out_size)
{
    const float* data      = (const float*)d_in[0];
    const float* noise     = (const float*)d_in[1];
    const float* rand_vals = (const float*)d_in[2];

    const int n_elems = in_sizes[0];          // 32*1024*2048
    const int rows    = n_elems / DDIM;       // 32768

    float* out_masked = (float*)d_out;
    float* out_inv    = (float*)d_out + (size_t)(out_size / 2);

    obsmask_kernel<<<rows, NTHREADS>>>(data, noise, rand_vals, out_masked, out_inv);
}

// round 16
// speedup vs baseline: 1.1198x; 1.1198x over previous
#include <cuda_runtime.h>

// Problem constants (fixed shapes: data/noise/rand are (32, 1024, 2048) fp32)
#define DDIM 2048
#define KSEL 512
#define NTHREADS 256
#define CAND_CAP 64
#define CAND_TARGET 48

__global__ __launch_bounds__(NTHREADS)
void obsmask_kernel(const float* __restrict__ data,
                    const float* __restrict__ noise,
                    const float* __restrict__ rand_vals,
                    float* __restrict__ out_masked,
                    float* __restrict__ out_inv)
{
    const int tid  = threadIdx.x;
    const int lane = tid & 31;
    const int wid  = tid >> 5;
    const size_t base = (size_t)blockIdx.x * DDIM;

    __shared__ unsigned s_wsum[NTHREADS / 32];
    __shared__ unsigned long long s_total;
    __shared__ float s_cval[CAND_CAP];
    __shared__ int   s_cidx[CAND_CAP];
    __shared__ int   s_ccnt;
    __shared__ unsigned char s_mask[DDIM];

    // ---- Issue ALL global loads up front (max MLP; Phase A hides latency) ----
    const float4* r4 = (const float4*)(rand_vals + base);
    const float4* d4 = (const float4*)(data  + base);
    const float4* n4 = (const float4*)(noise + base);

    float4 ra = r4[tid];
    float4 rb = r4[NTHREADS + tid];
    float4 da = d4[tid];
    float4 db = d4[NTHREADS + tid];
    float4 na = n4[tid];
    float4 nb = n4[NTHREADS + tid];

    float v[8] = { ra.x, ra.y, ra.z, ra.w, rb.x, rb.y, rb.z, rb.w };

    if (tid == 0) s_ccnt = 0;   // covered by Phase A's barriers (>=1 iteration always runs)

    // ---- Phase A: bisection for the k-th-largest bracket ----
    // Invariant: count(v > lo) = c_lo >= K,  count(v > hi) = c_hi < K.
    // rand ~ U[0,1): the 512th largest of 2048 concentrates at 0.75 (sd~0.0096),
    // so iteration 0 probes {0.735, 0.75, 0.765}; ~88% of rows finish in 1 round.
    // Branch logic only requires m1<m2<m3, so non-uniform data stays exact.
    float lo = 0.0f, hi = 1.0f;
    int c_lo = DDIM, c_hi = 0;

    for (int iter = 0; iter < 32 && (c_lo - c_hi) > CAND_TARGET; ++iter) {
        float m1, m2, m3;
        if (iter == 0) { m1 = 0.735f; m2 = 0.75f; m3 = 0.765f; }
        else {
            const float span = hi - lo;
            m1 = lo + 0.25f * span;
            m2 = lo + 0.50f * span;
            m3 = lo + 0.75f * span;
        }

        int c1 = 0, c2 = 0, c3 = 0;
        #pragma unroll
        for (int i = 0; i < 8; ++i) {
            c1 += (v[i] > m1);
            c2 += (v[i] > m2);
            c3 += (v[i] > m3);
        }
        // 10-bit fields: per-warp field sums <= 256, no cross-field carry.
        unsigned p = (unsigned)c1 | ((unsigned)c2 << 10) | ((unsigned)c3 << 20);
        p = __reduce_add_sync(0xffffffffu, p);   // REDUX.SUM: 1 instr per warp
        if (lane == 0) s_wsum[wid] = p;
        __syncthreads();
        if (tid == 0) {
            unsigned A = 0, B = 0, C = 0;
            #pragma unroll
            for (int w = 0; w < NTHREADS / 32; ++w) {
                const unsigned x = s_wsum[w];
                A += x & 1023u;
                B += (x >> 10) & 1023u;
                C += x >> 20;
            }
            s_total = (unsigned long long)A
                    | ((unsigned long long)B << 16)
                    | ((unsigned long long)C << 32);
        }
        __syncthreads();
        const unsigned long long t = s_total;
        const int C1 = (int)(t & 0xffffu);
        const int C2 = (int)((t >> 16) & 0xffffu);
        const int C3 = (int)((t >> 32) & 0xffffu);

        if (C1 < KSEL)      { hi = m1; c_hi = C1; }
        else if (C2 < KSEL) { lo = m1; c_lo = C1; hi = m2; c_hi = C2; }
        else if (C3 < KSEL) { lo = m2; c_lo = C2; hi = m3; c_hi = C3; }
        else                { lo = m3; c_lo = C3; }
        // Barrier protocol: s_wsum writes of iter i+1 are ordered after
        // barrier2 of iter i; s_total writes of iter i+1 happen after
        // barrier1 of i+1, past all readers of iter i's value.
    }

    // ---- Phase B: gather candidates in (lo, hi] ----
    const int r_need = KSEL - c_hi;   // 1 <= r_need <= #candidates
    #pragma unroll
    for (int i = 0; i < 8; ++i) {
        if (v[i] > lo && v[i] <= hi) {
            int slot = atomicAdd(&s_ccnt, 1);
            if (slot < CAND_CAP) {
                s_cval[slot] = v[i];
                s_cidx[slot] = (i < 4) ? (4 * tid + i) : (1024 + 4 * tid + (i - 4));
            }
        }
    }
    __syncthreads();

    // ---- Phase C: exact rank among candidates (ties -> lowest index first) ----
    const int c = min(s_ccnt, CAND_CAP);
    if (tid < c) {
        const float vi = s_cval[tid];
        const int   ii = s_cidx[tid];
        int rank = 0;
        for (int j = 0; j < c; ++j) {
            const float vj = s_cval[j];
            const int   ij = s_cidx[j];
            rank += (vj > vi) || (vj == vi && ij < ii);
        }
        s_mask[ii] = (rank < r_need) ? (unsigned char)1 : (unsigned char)0;
    }
    __syncthreads();

    // ---- Phase D: apply mask, write both outputs (coalesced float4) ----
    float dd[8] = { da.x, da.y, da.z, da.w, db.x, db.y, db.z, db.w };
    float nn[8] = { na.x, na.y, na.z, na.w, nb.x, nb.y, nb.z, nb.w };
    float om[8], oi[8];

    #pragma unroll
    for (int i = 0; i < 8; ++i) {
        bool m = (v[i] > hi);
        if (!m && v[i] > lo) {
            const int idx = (i < 4) ? (4 * tid + i) : (1024 + 4 * tid + (i - 4));
            m = (s_mask[idx] != 0);
        }
        om[i] = m ? 0.0f : fmaf(0.1f, nn[i], dd[i]);
        oi[i] = m ? 0.0f : 1.0f;
    }

    float4* om4 = (float4*)(out_masked + base);
    float4* oi4 = (float4*)(out_inv    + base);
    om4[tid]            = make_float4(om[0], om[1], om[2], om[3]);
    om4[NTHREADS + tid] = make_float4(om[4], om[5], om[6], om[7]);
    oi4[tid]            = make_float4(oi[0], oi[1], oi[2], oi[3]);
    oi4[NTHREADS + tid] = make_float4(oi[4], oi[5], oi[6], oi[7]);
}

extern "C" void kernel_launch(void* const* d_in, const int* in_sizes, int n_in,
                              void* d_out, int out_size)
{
    const float* data      = (const float*)d_in[0];
    const float* noise     = (const float*)d_in[1];
    const float* rand_vals = (const float*)d_in[2];

    const int n_elems = in_sizes[0];          // 32*1024*2048
    const int rows    = n_elems / DDIM;       // 32768

    float* out_masked = (float*)d_out;
    float* out_inv    = (float*)d_out + (size_t)(out_size / 2);

    obsmask_kernel<<<rows, NTHREADS>>>(data, noise, rand_vals, out_masked, out_inv);
}